// round 1
// baseline (speedup 1.0000x reference)
#include <cuda_runtime.h>
#include <cuda_bf16.h>
#include <cstdint>

// Problem constants (fixed by the dataset)
#define NNODES 50000
#define FDIM   256      // IN = HEADS*HID = OUT = 256
#define HEADS1 4
#define HID1   64
#define MAXE   900000   // E(800000) + N(50000) self loops, with margin

// ---------------- device scratch (no allocation allowed) ----------------
__device__ float g_h[(size_t)NNODES * FDIM];      // GEMM output (per layer, reused)
__device__ float g_act[(size_t)NNODES * FDIM];    // ELU(layer1 out) = layer2 input
__device__ float g_als[(size_t)NNODES * HEADS1];
__device__ float g_ald[(size_t)NNODES * HEADS1];
__device__ int   g_cnt[NNODES];
__device__ int   g_off[NNODES + 1];
__device__ int   g_cur[NNODES];
__device__ int   g_csr[MAXE];

// ---------------- CSR build ----------------
__global__ void zero_cnt_kernel(int n) {
    int i = blockIdx.x * blockDim.x + threadIdx.x;
    if (i < n) g_cnt[i] = 0;
}

__global__ void hist_kernel(const int* __restrict__ ei, int E, int n) {
    int i = blockIdx.x * blockDim.x + threadIdx.x;
    int ET = E + n;
    if (i >= ET) return;
    int dst = (i < E) ? ei[E + i] : (i - E);
    atomicAdd(&g_cnt[dst], 1);
}

__global__ void scan_kernel(int n) {
    __shared__ int sh[1024];
    __shared__ int sbase;
    if (threadIdx.x == 0) { sbase = 0; g_off[0] = 0; }
    __syncthreads();
    for (int start = 0; start < n; start += 1024) {
        int i = start + (int)threadIdx.x;
        int v = (i < n) ? g_cnt[i] : 0;
        sh[threadIdx.x] = v;
        __syncthreads();
        #pragma unroll
        for (int d = 1; d < 1024; d <<= 1) {
            int t2 = (threadIdx.x >= (unsigned)d) ? sh[threadIdx.x - d] : 0;
            __syncthreads();
            sh[threadIdx.x] += t2;
            __syncthreads();
        }
        if (i < n) g_off[i + 1] = sbase + sh[threadIdx.x];
        __syncthreads();
        if (threadIdx.x == 0) sbase += sh[1023];
        __syncthreads();
    }
}

__global__ void init_cursor_kernel(int n) {
    int i = blockIdx.x * blockDim.x + threadIdx.x;
    if (i < n) g_cur[i] = g_off[i];
}

__global__ void scatter_kernel(const int* __restrict__ ei, int E, int n) {
    int i = blockIdx.x * blockDim.x + threadIdx.x;
    int ET = E + n;
    if (i >= ET) return;
    int src, dst;
    if (i < E) { src = ei[i]; dst = ei[E + i]; }
    else       { src = i - E; dst = i - E; }
    int pos = atomicAdd(&g_cur[dst], 1);
    g_csr[pos] = src;
}

// ---------------- SGEMM: C[M,Nc] = A[M,K] * B[K,Nc]  (BM=BN=128, BK=8) ----------------
__global__ void sgemm128_kernel(const float* __restrict__ A, const float* __restrict__ B,
                                float* __restrict__ C, int M, int K, int Nc) {
    __shared__ float As[8][128];
    __shared__ float Bs[8][128];
    int t  = threadIdx.x;            // 256 threads
    int bx = blockIdx.x;             // col block
    int by = blockIdx.y;             // row block
    int row0 = by * 128, col0 = bx * 128;

    int a_row = t >> 1;              // 0..127
    int a_col = (t & 1) * 4;         // 0 or 4
    int b_row = t >> 5;              // 0..7
    int b_col = (t & 31) * 4;        // 0..124
    int tx = t & 15, ty = t >> 4;

    float acc[8][8];
    #pragma unroll
    for (int i = 0; i < 8; i++)
        #pragma unroll
        for (int j = 0; j < 8; j++) acc[i][j] = 0.f;

    for (int k0 = 0; k0 < K; k0 += 8) {
        int gr = row0 + a_row;
        float4 av = make_float4(0.f, 0.f, 0.f, 0.f);
        if (gr < M) av = *(const float4*)(A + (size_t)gr * K + k0 + a_col);
        As[a_col + 0][a_row] = av.x;
        As[a_col + 1][a_row] = av.y;
        As[a_col + 2][a_row] = av.z;
        As[a_col + 3][a_row] = av.w;
        float4 bv = *(const float4*)(B + (size_t)(k0 + b_row) * Nc + col0 + b_col);
        *(float4*)&Bs[b_row][b_col] = bv;
        __syncthreads();
        #pragma unroll
        for (int k = 0; k < 8; k++) {
            float a[8], b[8];
            #pragma unroll
            for (int i = 0; i < 8; i++) a[i] = As[k][ty * 8 + i];
            #pragma unroll
            for (int j = 0; j < 8; j++) b[j] = Bs[k][tx * 8 + j];
            #pragma unroll
            for (int i = 0; i < 8; i++)
                #pragma unroll
                for (int j = 0; j < 8; j++) acc[i][j] += a[i] * b[j];
        }
        __syncthreads();
    }
    #pragma unroll
    for (int i = 0; i < 8; i++) {
        int gr = row0 + ty * 8 + i;
        if (gr < M) {
            *(float4*)(C + (size_t)gr * Nc + col0 + tx * 8 + 0) =
                make_float4(acc[i][0], acc[i][1], acc[i][2], acc[i][3]);
            *(float4*)(C + (size_t)gr * Nc + col0 + tx * 8 + 4) =
                make_float4(acc[i][4], acc[i][5], acc[i][6], acc[i][7]);
        }
    }
}

// ---------------- attention logits: als/ald[n,h] = <h[n,h,:], att_src/dst[h,:]> ------
template <int HEADS, int F>
__global__ void att_kernel(const float* __restrict__ h,
                           const float* __restrict__ a_src,
                           const float* __restrict__ a_dst,
                           float* __restrict__ als, float* __restrict__ ald, int n) {
    constexpr int HID = F / HEADS;
    int gw   = (blockIdx.x * blockDim.x + threadIdx.x) >> 5;
    int lane = threadIdx.x & 31;
    int node = gw / HEADS;
    int hh   = gw % HEADS;
    if (node >= n) return;
    const float* hp = h + (size_t)node * F + hh * HID;
    float s1 = 0.f, s2 = 0.f;
    for (int i = lane; i < HID; i += 32) {
        float v = hp[i];
        s1 += v * a_src[hh * HID + i];
        s2 += v * a_dst[hh * HID + i];
    }
    #pragma unroll
    for (int o = 16; o; o >>= 1) {
        s1 += __shfl_xor_sync(0xFFFFFFFFu, s1, o);
        s2 += __shfl_xor_sync(0xFFFFFFFFu, s2, o);
    }
    if (lane == 0) {
        als[(size_t)node * HEADS + hh] = s1;
        ald[(size_t)node * HEADS + hh] = s2;
    }
}

// ---------------- per-dst softmax + aggregation (gather form) ----------------
// one 256-thread block per dst node; F=256 features total
template <int HEADS>
__global__ void agg_kernel(const float* __restrict__ h,
                           const float* __restrict__ als,
                           const float* __restrict__ ald,
                           const float* __restrict__ bias,
                           float* __restrict__ out, int n, int do_elu) {
    constexpr int F = 256;
    constexpr int HID = F / HEADS;
    constexpr int CHUNK = 64;
    int node = blockIdx.x;
    int t = threadIdx.x;
    int lane = t & 31, warp = t >> 5;
    int start = g_off[node], deg = g_off[node + 1] - start;

    __shared__ float sm[HEADS];
    __shared__ float sinv[HEADS];
    __shared__ float swarp[8 * HEADS];
    __shared__ int   ssrc[CHUNK];
    __shared__ float sw[CHUNK * HEADS];

    float aldn[HEADS];
    #pragma unroll
    for (int hh = 0; hh < HEADS; hh++) aldn[hh] = ald[(size_t)node * HEADS + hh];

    // ---- phase A: per-head max over incoming edges ----
    float lmax[HEADS];
    #pragma unroll
    for (int hh = 0; hh < HEADS; hh++) lmax[hh] = -1e30f;
    for (int j = t; j < deg; j += 256) {
        int s = g_csr[start + j];
        #pragma unroll
        for (int hh = 0; hh < HEADS; hh++) {
            float e = als[(size_t)s * HEADS + hh] + aldn[hh];
            e = (e > 0.f) ? e : 0.2f * e;
            lmax[hh] = fmaxf(lmax[hh], e);
        }
    }
    #pragma unroll
    for (int hh = 0; hh < HEADS; hh++)
        #pragma unroll
        for (int o = 16; o; o >>= 1)
            lmax[hh] = fmaxf(lmax[hh], __shfl_xor_sync(0xFFFFFFFFu, lmax[hh], o));
    if (lane == 0)
        #pragma unroll
        for (int hh = 0; hh < HEADS; hh++) swarp[warp * HEADS + hh] = lmax[hh];
    __syncthreads();
    if (t < HEADS) {
        float m = -1e30f;
        #pragma unroll
        for (int w = 0; w < 8; w++) m = fmaxf(m, swarp[w * HEADS + t]);
        sm[t] = m;
    }
    __syncthreads();

    // ---- phase B: per-head sum of exp ----
    float lsum[HEADS];
    #pragma unroll
    for (int hh = 0; hh < HEADS; hh++) lsum[hh] = 0.f;
    for (int j = t; j < deg; j += 256) {
        int s = g_csr[start + j];
        #pragma unroll
        for (int hh = 0; hh < HEADS; hh++) {
            float e = als[(size_t)s * HEADS + hh] + aldn[hh];
            e = (e > 0.f) ? e : 0.2f * e;
            lsum[hh] += __expf(e - sm[hh]);
        }
    }
    #pragma unroll
    for (int hh = 0; hh < HEADS; hh++)
        #pragma unroll
        for (int o = 16; o; o >>= 1)
            lsum[hh] += __shfl_xor_sync(0xFFFFFFFFu, lsum[hh], o);
    if (lane == 0)
        #pragma unroll
        for (int hh = 0; hh < HEADS; hh++) swarp[warp * HEADS + hh] = lsum[hh];
    __syncthreads();
    if (t < HEADS) {
        float s = 0.f;
        #pragma unroll
        for (int w = 0; w < 8; w++) s += swarp[w * HEADS + t];
        sinv[t] = 1.f / (s + 1e-16f);
    }
    __syncthreads();

    // ---- phase C: weighted feature gather ----
    int f = t;
    int hh_f = f / HID;
    float acc = 0.f;
    for (int base = 0; base < deg; base += CHUNK) {
        int cnt = min(CHUNK, deg - base);
        if (t < cnt) {
            int s = g_csr[start + base + t];
            ssrc[t] = s;
            #pragma unroll
            for (int hh = 0; hh < HEADS; hh++) {
                float e = als[(size_t)s * HEADS + hh] + aldn[hh];
                e = (e > 0.f) ? e : 0.2f * e;
                sw[t * HEADS + hh] = __expf(e - sm[hh]) * sinv[hh];
            }
        }
        __syncthreads();
        for (int j = 0; j < cnt; j++) {
            acc += h[(size_t)ssrc[j] * F + f] * sw[j * HEADS + hh_f];
        }
        __syncthreads();
    }
    float o = acc + bias[f];
    if (do_elu) o = (o > 0.f) ? o : (__expf(o) - 1.f);
    out[(size_t)node * F + f] = o;
}

// ---------------- launch ----------------
extern "C" void kernel_launch(void* const* d_in, const int* in_sizes, int n_in,
                              void* d_out, int out_size) {
    const float* x        = (const float*)d_in[0];
    const int*   ei       = (const int*)  d_in[1];
    const float* W1       = (const float*)d_in[2];
    const float* att_src1 = (const float*)d_in[3];
    const float* att_dst1 = (const float*)d_in[4];
    const float* b1       = (const float*)d_in[5];
    const float* W2       = (const float*)d_in[6];
    const float* att_src2 = (const float*)d_in[7];
    const float* att_dst2 = (const float*)d_in[8];
    const float* b2       = (const float*)d_in[9];
    float* out = (float*)d_out;

    int n  = in_sizes[0] / FDIM;     // 50000
    int E  = in_sizes[1] / 2;        // 800000
    int ET = E + n;

    float *p_h, *p_act, *p_als, *p_ald;
    cudaGetSymbolAddress((void**)&p_h,   g_h);
    cudaGetSymbolAddress((void**)&p_act, g_act);
    cudaGetSymbolAddress((void**)&p_als, g_als);
    cudaGetSymbolAddress((void**)&p_ald, g_ald);

    // ---- CSR build (shared by both layers) ----
    zero_cnt_kernel<<<(n + 255) / 256, 256>>>(n);
    hist_kernel<<<(ET + 255) / 256, 256>>>(ei, E, n);
    scan_kernel<<<1, 1024>>>(n);
    init_cursor_kernel<<<(n + 255) / 256, 256>>>(n);
    scatter_kernel<<<(ET + 255) / 256, 256>>>(ei, E, n);

    dim3 gemm_grid(FDIM / 128, (n + 127) / 128);

    // ---- layer 1 ----
    sgemm128_kernel<<<gemm_grid, 256>>>(x, W1, p_h, n, FDIM, FDIM);
    {
        int warps = n * HEADS1;
        att_kernel<HEADS1, FDIM><<<(warps * 32 + 255) / 256, 256>>>(
            p_h, att_src1, att_dst1, p_als, p_ald, n);
    }
    agg_kernel<HEADS1><<<n, 256>>>(p_h, p_als, p_ald, b1, p_act, n, /*do_elu=*/1);

    // ---- layer 2 ----
    sgemm128_kernel<<<gemm_grid, 256>>>(p_act, W2, p_h, n, FDIM, FDIM);
    {
        int warps = n * 1;
        att_kernel<1, FDIM><<<(warps * 32 + 255) / 256, 256>>>(
            p_h, att_src2, att_dst2, p_als, p_ald, n);
    }
    agg_kernel<1><<<n, 256>>>(p_h, p_als, p_ald, b2, out, n, /*do_elu=*/0);
}

// round 3
// speedup vs baseline: 1.2737x; 1.2737x over previous
#include <cuda_runtime.h>
#include <cuda_bf16.h>
#include <cstdint>

// Problem constants (fixed by the dataset)
#define NNODES 50000
#define FDIM   256
#define HEADS1 4
#define MAXE   900000
#define MPAD   50048      // 391 * 128

// ---------------- device scratch ----------------
__device__ float g_h[(size_t)MPAD * FDIM];        // GEMM output (per layer, reused)
__device__ float g_act[(size_t)NNODES * FDIM];    // ELU(layer1 out) = layer2 input
__device__ float g_als[(size_t)NNODES * HEADS1];
__device__ float g_ald[(size_t)NNODES * HEADS1];
__device__ int   g_cnt[NNODES];
__device__ int   g_off[NNODES + 1];
__device__ int   g_cur[NNODES];
__device__ int   g_csr[MAXE];
// split-bf16 operands in mma-fragment order
__device__ __align__(16) __nv_bfloat16 g_ahi[(size_t)MPAD * FDIM];
__device__ __align__(16) __nv_bfloat16 g_alo[(size_t)MPAD * FDIM];
__device__ __align__(16) __nv_bfloat16 g_b1hi[FDIM * FDIM];
__device__ __align__(16) __nv_bfloat16 g_b1lo[FDIM * FDIM];
__device__ __align__(16) __nv_bfloat16 g_b2hi[FDIM * FDIM];
__device__ __align__(16) __nv_bfloat16 g_b2lo[FDIM * FDIM];

// ---------------- HMMA helper ----------------
__device__ __forceinline__ void mma16816(float* c, const uint4& a, const uint2& b) {
    asm volatile(
        "mma.sync.aligned.m16n8k16.row.col.f32.bf16.bf16.f32 "
        "{%0,%1,%2,%3}, {%4,%5,%6,%7}, {%8,%9}, {%0,%1,%2,%3};"
        : "+f"(c[0]), "+f"(c[1]), "+f"(c[2]), "+f"(c[3])
        : "r"(a.x), "r"(a.y), "r"(a.z), "r"(a.w), "r"(b.x), "r"(b.y));
}

// ---------------- fragment-order converts ----------------
// A: fp32 [rows][256] -> hi/lo bf16, u32-packed fragment layout:
//   u32 index = ((mt*16 + kstep)*32 + lane)*4 + r
//   lane = g*4 + tig;  r = (rowlo>=8) | ((klo>=8)<<1)
//   row = mt*16 + (r&1)*8 + g ; k = kstep*16 + ((r>>1)&1)*8 + tig*2 (+pair)
__global__ void conv_afrag_kernel(const float* __restrict__ src,
                                  uint32_t* __restrict__ hi, uint32_t* __restrict__ lo, int n) {
    int u = blockIdx.x * blockDim.x + threadIdx.x;   // one u32 output (2 bf16)
    if (u >= MPAD * FDIM / 2) return;
    int r    = u & 3;
    int lane = (u >> 2) & 31;
    int blk  = u >> 7;              // mt*16 + kstep
    int kstep = blk & 15;
    int mt    = blk >> 4;
    int g = lane >> 2, tig = lane & 3;
    int row = mt * 16 + (r & 1) * 8 + g;
    int k   = kstep * 16 + ((r >> 1) & 1) * 8 + tig * 2;
    float v0 = 0.f, v1 = 0.f;
    if (row < n) {
        const float* p = src + (size_t)row * 256 + k;
        v0 = p[0]; v1 = p[1];
    }
    __nv_bfloat16 h0 = __float2bfloat16(v0);
    __nv_bfloat16 h1 = __float2bfloat16(v1);
    __nv_bfloat16 l0 = __float2bfloat16(v0 - __bfloat162float(h0));
    __nv_bfloat16 l1 = __float2bfloat16(v1 - __bfloat162float(h1));
    hi[u] = (uint32_t)__bfloat16_as_ushort(h0) | ((uint32_t)__bfloat16_as_ushort(h1) << 16);
    lo[u] = (uint32_t)__bfloat16_as_ushort(l0) | ((uint32_t)__bfloat16_as_ushort(l1) << 16);
}

// W: fp32 [256(k)][256(n)] -> hi/lo bf16 fragment layout:
//   u32 index = ((ntile*16 + kstep)*32 + lane)*2 + r
//   n = ntile*8 + g ; k = kstep*16 + r*8 + tig*2 (+pair)
__global__ void conv_wfrag_kernel(const float* __restrict__ W,
                                  uint32_t* __restrict__ hi, uint32_t* __restrict__ lo) {
    int u = blockIdx.x * blockDim.x + threadIdx.x;
    if (u >= FDIM * FDIM / 2) return;
    int r    = u & 1;
    int lane = (u >> 1) & 31;
    int blk  = u >> 6;              // ntile*16 + kstep
    int kstep = blk & 15;
    int ntile = blk >> 4;
    int g = lane >> 2, tig = lane & 3;
    int nn = ntile * 8 + g;
    int k  = kstep * 16 + r * 8 + tig * 2;
    float v0 = W[(size_t)k * 256 + nn];
    float v1 = W[(size_t)(k + 1) * 256 + nn];
    __nv_bfloat16 h0 = __float2bfloat16(v0);
    __nv_bfloat16 h1 = __float2bfloat16(v1);
    __nv_bfloat16 l0 = __float2bfloat16(v0 - __bfloat162float(h0));
    __nv_bfloat16 l1 = __float2bfloat16(v1 - __bfloat162float(h1));
    hi[u] = (uint32_t)__bfloat16_as_ushort(h0) | ((uint32_t)__bfloat16_as_ushort(h1) << 16);
    lo[u] = (uint32_t)__bfloat16_as_ushort(l0) | ((uint32_t)__bfloat16_as_ushort(l1) << 16);
}

// ---------------- HMMA GEMM: C[MPAD,256] = A * W (split-bf16, 3 products) --------
// grid (2, 391), 256 threads = 8 warps (4 m-warps x 2 n-warps)
// warp tile 32x64 = 2 mtiles x 8 ntiles of m16n8k16, K loop = 16 ksteps
__global__ void __launch_bounds__(256)
gemm_mma_kernel(const uint4* __restrict__ a_hi, const uint4* __restrict__ a_lo,
                const uint2* __restrict__ b_hi, const uint2* __restrict__ b_lo,
                float* __restrict__ C) {
    int t = threadIdx.x, lane = t & 31, wid = t >> 5;
    int wm = wid & 3, wn = wid >> 2;
    int mt_base = blockIdx.y * 8 + wm * 2;     // 16-row tiles
    int nt_base = blockIdx.x * 16 + wn * 8;    // 8-col tiles

    float acc[2][8][4];
    #pragma unroll
    for (int m = 0; m < 2; m++)
        #pragma unroll
        for (int j = 0; j < 8; j++)
            #pragma unroll
            for (int q = 0; q < 4; q++) acc[m][j][q] = 0.f;

    #pragma unroll 2
    for (int ks = 0; ks < 16; ks++) {
        uint4 ah[2], al[2];
        #pragma unroll
        for (int m = 0; m < 2; m++) {
            int idx = ((mt_base + m) * 16 + ks) * 32 + lane;
            ah[m] = a_hi[idx];
            al[m] = a_lo[idx];
        }
        uint2 bh[8], bl[8];
        #pragma unroll
        for (int j = 0; j < 8; j++) {
            int idx = ((nt_base + j) * 16 + ks) * 32 + lane;
            bh[j] = b_hi[idx];
            bl[j] = b_lo[idx];
        }
        #pragma unroll
        for (int m = 0; m < 2; m++)
            #pragma unroll
            for (int j = 0; j < 8; j++) {
                mma16816(acc[m][j], ah[m], bh[j]);
                mma16816(acc[m][j], ah[m], bl[j]);
                mma16816(acc[m][j], al[m], bh[j]);
            }
    }

    int g = lane >> 2, tt = lane & 3;
    #pragma unroll
    for (int m = 0; m < 2; m++) {
        int r0 = (mt_base + m) * 16 + g;
        #pragma unroll
        for (int j = 0; j < 8; j++) {
            int col = (nt_base + j) * 8 + tt * 2;
            *(float2*)(C + (size_t)r0 * 256 + col)       = make_float2(acc[m][j][0], acc[m][j][1]);
            *(float2*)(C + (size_t)(r0 + 8) * 256 + col) = make_float2(acc[m][j][2], acc[m][j][3]);
        }
    }
}

// ---------------- CSR build ----------------
__global__ void zero_cnt_kernel(int n) {
    int i = blockIdx.x * blockDim.x + threadIdx.x;
    if (i < n) g_cnt[i] = 0;
}
__global__ void hist_kernel(const int* __restrict__ ei, int E, int n) {
    int i = blockIdx.x * blockDim.x + threadIdx.x;
    int ET = E + n;
    if (i >= ET) return;
    int dst = (i < E) ? ei[E + i] : (i - E);
    atomicAdd(&g_cnt[dst], 1);
}
__global__ void scan_kernel(int n) {
    __shared__ int sh[1024];
    __shared__ int sbase;
    if (threadIdx.x == 0) { sbase = 0; g_off[0] = 0; }
    __syncthreads();
    for (int start = 0; start < n; start += 1024) {
        int i = start + (int)threadIdx.x;
        int v = (i < n) ? g_cnt[i] : 0;
        sh[threadIdx.x] = v;
        __syncthreads();
        #pragma unroll
        for (int d = 1; d < 1024; d <<= 1) {
            int t2 = (threadIdx.x >= (unsigned)d) ? sh[threadIdx.x - d] : 0;
            __syncthreads();
            sh[threadIdx.x] += t2;
            __syncthreads();
        }
        if (i < n) {
            int incl = sbase + sh[threadIdx.x];
            g_off[i + 1] = incl;
            g_cur[i] = incl - v;
        }
        __syncthreads();
        if (threadIdx.x == 0) sbase += sh[1023];
        __syncthreads();
    }
}
__global__ void scatter_kernel(const int* __restrict__ ei, int E, int n) {
    int i = blockIdx.x * blockDim.x + threadIdx.x;
    int ET = E + n;
    if (i >= ET) return;
    int src, dst;
    if (i < E) { src = ei[i]; dst = ei[E + i]; }
    else       { src = i - E; dst = i - E; }
    int pos = atomicAdd(&g_cur[dst], 1);
    g_csr[pos] = src;
}

// ---------------- attention logits ----------------
template <int HEADS, int F>
__global__ void att_kernel(const float* __restrict__ h,
                           const float* __restrict__ a_src,
                           const float* __restrict__ a_dst,
                           float* __restrict__ als, float* __restrict__ ald, int n) {
    constexpr int HID = F / HEADS;
    int gw   = (blockIdx.x * blockDim.x + threadIdx.x) >> 5;
    int lane = threadIdx.x & 31;
    int node = gw / HEADS;
    int hh   = gw % HEADS;
    if (node >= n) return;
    const float* hp = h + (size_t)node * F + hh * HID;
    float s1 = 0.f, s2 = 0.f;
    for (int i = lane; i < HID; i += 32) {
        float v = hp[i];
        s1 += v * a_src[hh * HID + i];
        s2 += v * a_dst[hh * HID + i];
    }
    #pragma unroll
    for (int o = 16; o; o >>= 1) {
        s1 += __shfl_xor_sync(0xFFFFFFFFu, s1, o);
        s2 += __shfl_xor_sync(0xFFFFFFFFu, s2, o);
    }
    if (lane == 0) {
        als[(size_t)node * HEADS + hh] = s1;
        ald[(size_t)node * HEADS + hh] = s2;
    }
}

// ---------------- per-dst softmax + aggregation ----------------
template <int HEADS>
__global__ void agg_kernel(const float* __restrict__ h,
                           const float* __restrict__ als,
                           const float* __restrict__ ald,
                           const float* __restrict__ bias,
                           float* __restrict__ out, int n, int do_elu) {
    constexpr int F = 256;
    constexpr int HID = F / HEADS;
    constexpr int CHUNK = 64;
    int node = blockIdx.x;
    int t = threadIdx.x;
    int lane = t & 31, warp = t >> 5;
    int start = g_off[node], deg = g_off[node + 1] - start;

    __shared__ float sm[HEADS];
    __shared__ float sinv[HEADS];
    __shared__ float swarp[8 * HEADS];
    __shared__ int   ssrc[CHUNK];
    __shared__ float sw[CHUNK * HEADS];

    float aldn[HEADS];
    #pragma unroll
    for (int hh = 0; hh < HEADS; hh++) aldn[hh] = ald[(size_t)node * HEADS + hh];

    float lmax[HEADS];
    #pragma unroll
    for (int hh = 0; hh < HEADS; hh++) lmax[hh] = -1e30f;
    for (int j = t; j < deg; j += 256) {
        int s = g_csr[start + j];
        #pragma unroll
        for (int hh = 0; hh < HEADS; hh++) {
            float e = als[(size_t)s * HEADS + hh] + aldn[hh];
            e = (e > 0.f) ? e : 0.2f * e;
            lmax[hh] = fmaxf(lmax[hh], e);
        }
    }
    #pragma unroll
    for (int hh = 0; hh < HEADS; hh++)
        #pragma unroll
        for (int o = 16; o; o >>= 1)
            lmax[hh] = fmaxf(lmax[hh], __shfl_xor_sync(0xFFFFFFFFu, lmax[hh], o));
    if (lane == 0)
        #pragma unroll
        for (int hh = 0; hh < HEADS; hh++) swarp[warp * HEADS + hh] = lmax[hh];
    __syncthreads();
    if (t < HEADS) {
        float m = -1e30f;
        #pragma unroll
        for (int w = 0; w < 8; w++) m = fmaxf(m, swarp[w * HEADS + t]);
        sm[t] = m;
    }
    __syncthreads();

    float lsum[HEADS];
    #pragma unroll
    for (int hh = 0; hh < HEADS; hh++) lsum[hh] = 0.f;
    for (int j = t; j < deg; j += 256) {
        int s = g_csr[start + j];
        #pragma unroll
        for (int hh = 0; hh < HEADS; hh++) {
            float e = als[(size_t)s * HEADS + hh] + aldn[hh];
            e = (e > 0.f) ? e : 0.2f * e;
            lsum[hh] += __expf(e - sm[hh]);
        }
    }
    #pragma unroll
    for (int hh = 0; hh < HEADS; hh++)
        #pragma unroll
        for (int o = 16; o; o >>= 1)
            lsum[hh] += __shfl_xor_sync(0xFFFFFFFFu, lsum[hh], o);
    if (lane == 0)
        #pragma unroll
        for (int hh = 0; hh < HEADS; hh++) swarp[warp * HEADS + hh] = lsum[hh];
    __syncthreads();
    if (t < HEADS) {
        float s = 0.f;
        #pragma unroll
        for (int w = 0; w < 8; w++) s += swarp[w * HEADS + t];
        sinv[t] = 1.f / (s + 1e-16f);
    }
    __syncthreads();

    int f = t;
    int hh_f = f / HID;
    float acc = 0.f;
    for (int base = 0; base < deg; base += CHUNK) {
        int cnt = min(CHUNK, deg - base);
        if (t < cnt) {
            int s = g_csr[start + base + t];
            ssrc[t] = s;
            #pragma unroll
            for (int hh = 0; hh < HEADS; hh++) {
                float e = als[(size_t)s * HEADS + hh] + aldn[hh];
                e = (e > 0.f) ? e : 0.2f * e;
                sw[t * HEADS + hh] = __expf(e - sm[hh]) * sinv[hh];
            }
        }
        __syncthreads();
        for (int j = 0; j < cnt; j++) {
            acc += h[(size_t)ssrc[j] * F + f] * sw[j * HEADS + hh_f];
        }
        __syncthreads();
    }
    float o = acc + bias[f];
    if (do_elu) o = (o > 0.f) ? o : (__expf(o) - 1.f);
    out[(size_t)node * F + f] = o;
}

// ---------------- launch ----------------
extern "C" void kernel_launch(void* const* d_in, const int* in_sizes, int n_in,
                              void* d_out, int out_size) {
    const float* x        = (const float*)d_in[0];
    const int*   ei       = (const int*)  d_in[1];
    const float* W1       = (const float*)d_in[2];
    const float* att_src1 = (const float*)d_in[3];
    const float* att_dst1 = (const float*)d_in[4];
    const float* b1       = (const float*)d_in[5];
    const float* W2       = (const float*)d_in[6];
    const float* att_src2 = (const float*)d_in[7];
    const float* att_dst2 = (const float*)d_in[8];
    const float* b2       = (const float*)d_in[9];
    float* out = (float*)d_out;

    int n  = in_sizes[0] / FDIM;   // 50000
    int E  = in_sizes[1] / 2;      // 800000
    int ET = E + n;

    float *p_h, *p_act, *p_als, *p_ald;
    __nv_bfloat16 *p_ahi, *p_alo, *p_b1hi, *p_b1lo, *p_b2hi, *p_b2lo;
    cudaGetSymbolAddress((void**)&p_h,    g_h);
    cudaGetSymbolAddress((void**)&p_act,  g_act);
    cudaGetSymbolAddress((void**)&p_als,  g_als);
    cudaGetSymbolAddress((void**)&p_ald,  g_ald);
    cudaGetSymbolAddress((void**)&p_ahi,  g_ahi);
    cudaGetSymbolAddress((void**)&p_alo,  g_alo);
    cudaGetSymbolAddress((void**)&p_b1hi, g_b1hi);
    cudaGetSymbolAddress((void**)&p_b1lo, g_b1lo);
    cudaGetSymbolAddress((void**)&p_b2hi, g_b2hi);
    cudaGetSymbolAddress((void**)&p_b2lo, g_b2lo);

    // ---- CSR build ----
    zero_cnt_kernel<<<(n + 255) / 256, 256>>>(n);
    hist_kernel<<<(ET + 255) / 256, 256>>>(ei, E, n);
    scan_kernel<<<1, 1024>>>(n);
    scatter_kernel<<<(ET + 255) / 256, 256>>>(ei, E, n);

    // ---- weight converts (fragment order) ----
    int wu = FDIM * FDIM / 2;
    conv_wfrag_kernel<<<(wu + 255) / 256, 256>>>(W1, (uint32_t*)p_b1hi, (uint32_t*)p_b1lo);
    conv_wfrag_kernel<<<(wu + 255) / 256, 256>>>(W2, (uint32_t*)p_b2hi, (uint32_t*)p_b2lo);

    int au = MPAD * FDIM / 2;
    dim3 gemm_grid(2, MPAD / 128);

    // ---- layer 1 ----
    conv_afrag_kernel<<<(au + 255) / 256, 256>>>(x, (uint32_t*)p_ahi, (uint32_t*)p_alo, n);
    gemm_mma_kernel<<<gemm_grid, 256>>>((const uint4*)p_ahi, (const uint4*)p_alo,
                                        (const uint2*)p_b1hi, (const uint2*)p_b1lo, p_h);
    {
        int warps = n * HEADS1;
        att_kernel<HEADS1, FDIM><<<(warps * 32 + 255) / 256, 256>>>(
            p_h, att_src1, att_dst1, p_als, p_ald, n);
    }
    agg_kernel<HEADS1><<<n, 256>>>(p_h, p_als, p_ald, b1, p_act, n, 1);

    // ---- layer 2 ----
    conv_afrag_kernel<<<(au + 255) / 256, 256>>>(p_act, (uint32_t*)p_ahi, (uint32_t*)p_alo, n);
    gemm_mma_kernel<<<gemm_grid, 256>>>((const uint4*)p_ahi, (const uint4*)p_alo,
                                        (const uint2*)p_b2hi, (const uint2*)p_b2lo, p_h);
    {
        int warps = n;
        att_kernel<1, FDIM><<<(warps * 32 + 255) / 256, 256>>>(
            p_h, att_src2, att_dst2, p_als, p_ald, n);
    }
    agg_kernel<1><<<n, 256>>>(p_h, p_als, p_ald, b2, out, n, 0);
}